// round 5
// baseline (speedup 1.0000x reference)
#include <cuda_runtime.h>
#include <math.h>

// Problem constants
#define BB   32
#define CC   256
#define CQ   64
#define HW   4096                 // 64*64
#define CHW  (CC*HW)              // 1048576
#define DD   (CQ*HW)              // 262144

// Scratch (device globals — no allocation allowed)
__device__ float g_Q[(size_t)BB*CQ*HW];       // [b][o][p]
__device__ float g_K[(size_t)BB*CQ*HW];       // [b][o][p]
__device__ float g_energy[BB*BB];
__device__ float g_att[BB*BB];
__device__ float g_y[(size_t)BB*CHW];         // [i][c][p] = sum_j att[i,j] x0[j,c,p]

// ---------------------------------------------------------------------------
__global__ void k_zero_energy() {
    int t = threadIdx.x;
    if (t < BB*BB) g_energy[t] = 0.0f;
}

// ---------------------------------------------------------------------------
// Q = Wq x0 + bq ; K = Wk x1 + bk   (blockIdx.z selects which)
// Per block: 64 outputs x 256 pixels, 256 threads, 8x8 register tile each.
__global__ __launch_bounds__(256) void k_proj_qk(
    const float* __restrict__ x0, const float* __restrict__ x1,
    const float* __restrict__ Wq, const float* __restrict__ bq,
    const float* __restrict__ Wk, const float* __restrict__ bk)
{
    const int which = blockIdx.z;
    const float* __restrict__ x    = which ? x1 : x0;
    const float* __restrict__ W    = which ? Wk : Wq;
    const float* __restrict__ bias = which ? bk : bq;
    float* __restrict__ outp       = which ? g_K : g_Q;

    const int b  = blockIdx.y;
    const int p0 = blockIdx.x * 256;
    const int t  = threadIdx.x;
    const int po = t & 31;        // pixel group   (p = p0 + po + 32k), lane-contig
    const int oi = t >> 5;        // output group  (o = oi + 8u), warp-uniform

    __shared__ float xs[32][256];
    __shared__ float ws[64][32];

    float acc[8][8];
    #pragma unroll
    for (int u = 0; u < 8; u++)
        #pragma unroll
        for (int k = 0; k < 8; k++) acc[u][k] = 0.0f;

    const float* xb = x + (size_t)b * CHW + p0;

    for (int cc = 0; cc < CC; cc += 32) {
        __syncthreads();
        // 32x256 x-tile = 2048 float4, 256 threads -> 8 iters
        #pragma unroll
        for (int r = 0; r < 8; r++) {
            int idx = r * 256 + t;
            int c = idx >> 6, q4 = idx & 63;
            reinterpret_cast<float4*>(xs[c])[q4] =
                reinterpret_cast<const float4*>(xb + (size_t)(cc + c) * HW)[q4];
        }
        // 64x32 W-tile = 512 float4, 256 threads -> 2 iters
        #pragma unroll
        for (int r = 0; r < 2; r++) {
            int idx = r * 256 + t;
            int o = idx >> 3, q4 = idx & 7;
            reinterpret_cast<float4*>(ws[o])[q4] =
                reinterpret_cast<const float4*>(W + o * CC + cc)[q4];
        }
        __syncthreads();

        #pragma unroll
        for (int c = 0; c < 32; c++) {
            float xv[8], wv[8];
            #pragma unroll
            for (int k = 0; k < 8; k++) xv[k] = xs[c][po + 32*k];
            #pragma unroll
            for (int u = 0; u < 8; u++) wv[u] = ws[oi + 8*u][c];
            #pragma unroll
            for (int u = 0; u < 8; u++)
                #pragma unroll
                for (int k = 0; k < 8; k++) acc[u][k] += wv[u] * xv[k];
        }
    }

    #pragma unroll
    for (int u = 0; u < 8; u++) {
        int o = oi + 8*u;
        float bb = bias[o];
        float* op = outp + ((size_t)b * CQ + o) * HW + p0;
        #pragma unroll
        for (int k = 0; k < 8; k++) op[po + 32*k] = acc[u][k] + bb;
    }
}

// ---------------------------------------------------------------------------
// energy[i][j] += sum_d K[i,d] * Q[j,d]   (32x32 output, D=262144)
// grid 512 blocks, each handles 512 d (8 chunks of 64), atomicAdd at end.
__global__ __launch_bounds__(256) void k_energy()
{
    __shared__ float Ks[32][65];
    __shared__ float Qs[32][65];
    const int t  = threadIdx.x;
    const int jj = t & 15;
    const int ii = t >> 4;        // 0..15

    float acc[2][2] = {{0.f,0.f},{0.f,0.f}};
    const int d0 = blockIdx.x * 512;

    for (int ch = 0; ch < 8; ch++) {
        const int db = d0 + ch * 64;
        __syncthreads();
        #pragma unroll
        for (int r = 0; r < 8; r++) {
            int idx = r * 256 + t;
            int row = idx >> 6, dd = idx & 63;
            Ks[row][dd] = g_K[(size_t)row * DD + db + dd];
            Qs[row][dd] = g_Q[(size_t)row * DD + db + dd];
        }
        __syncthreads();
        #pragma unroll
        for (int dd = 0; dd < 64; dd++) {
            float k0 = Ks[ii][dd],      k1 = Ks[ii + 16][dd];
            float q0 = Qs[jj][dd],      q1 = Qs[jj + 16][dd];
            acc[0][0] += k0 * q0;  acc[0][1] += k0 * q1;
            acc[1][0] += k1 * q0;  acc[1][1] += k1 * q1;
        }
    }
    #pragma unroll
    for (int u = 0; u < 2; u++)
        #pragma unroll
        for (int v = 0; v < 2; v++)
            atomicAdd(&g_energy[(ii + 16*u) * BB + (jj + 16*v)], acc[u][v]);
}

// ---------------------------------------------------------------------------
// attention[i][j] = softmax_j(energy[i][j]); also write to d_out tail.
__global__ void k_softmax(float* __restrict__ att_out)
{
    int i = threadIdx.x;
    if (i >= BB) return;
    float e[BB];
    float m = -INFINITY;
    #pragma unroll
    for (int j = 0; j < BB; j++) { e[j] = g_energy[i*BB + j]; m = fmaxf(m, e[j]); }
    float s = 0.f;
    #pragma unroll
    for (int j = 0; j < BB; j++) { e[j] = expf(e[j] - m); s += e[j]; }
    float inv = 1.0f / s;
    #pragma unroll
    for (int j = 0; j < BB; j++) {
        float a = e[j] * inv;
        g_att[i*BB + j] = a;
        if (att_out) att_out[i*BB + j] = a;
    }
}

// ---------------------------------------------------------------------------
// y[i,cp] = sum_j att[i,j] * x0[j,cp]
__global__ __launch_bounds__(256) void k_mix(const float* __restrict__ x0)
{
    __shared__ float att_s[BB*BB];
    const int t = threadIdx.x;
    #pragma unroll
    for (int r = 0; r < 4; r++) att_s[r*256 + t] = g_att[r*256 + t];
    __syncthreads();

    const size_t cp = (size_t)blockIdx.x * 256 + t;
    float acc[BB];
    #pragma unroll
    for (int i = 0; i < BB; i++) acc[i] = 0.0f;

    #pragma unroll
    for (int j = 0; j < BB; j++) {
        float v = x0[(size_t)j * CHW + cp];
        #pragma unroll
        for (int i = 0; i < BB; i++) acc[i] += att_s[i*BB + j] * v;
    }
    #pragma unroll
    for (int i = 0; i < BB; i++) g_y[(size_t)i * CHW + cp] = acc[i];
}

// ---------------------------------------------------------------------------
// out[i,o,p] = gamma*(sum_c Wv[o,c] y[i,c,p] + bv[o]) + x1[i,o,p]
// Per block: 64 outputs (blockIdx.z tile of 4) x 256 pixels, 256 threads.
__global__ __launch_bounds__(256) void k_out(
    const float* __restrict__ x1, const float* __restrict__ Wv,
    const float* __restrict__ bv, const float* __restrict__ gamma,
    float* __restrict__ outp)
{
    const int b  = blockIdx.y;
    const int ot = blockIdx.z * 64;
    const int p0 = blockIdx.x * 256;
    const int t  = threadIdx.x;
    const int po = t & 31;
    const int oi = t >> 5;

    __shared__ float xs[32][256];
    __shared__ float ws[64][32];

    float acc[8][8];
    #pragma unroll
    for (int u = 0; u < 8; u++)
        #pragma unroll
        for (int k = 0; k < 8; k++) acc[u][k] = 0.0f;

    const float* yb = g_y + (size_t)b * CHW + p0;

    for (int cc = 0; cc < CC; cc += 32) {
        __syncthreads();
        #pragma unroll
        for (int r = 0; r < 8; r++) {
            int idx = r * 256 + t;
            int c = idx >> 6, q4 = idx & 63;
            reinterpret_cast<float4*>(xs[c])[q4] =
                reinterpret_cast<const float4*>(yb + (size_t)(cc + c) * HW)[q4];
        }
        #pragma unroll
        for (int r = 0; r < 2; r++) {
            int idx = r * 256 + t;
            int o = idx >> 3, q4 = idx & 7;
            reinterpret_cast<float4*>(ws[o])[q4] =
                reinterpret_cast<const float4*>(Wv + (ot + o) * CC + cc)[q4];
        }
        __syncthreads();

        #pragma unroll
        for (int c = 0; c < 32; c++) {
            float xv[8], wv[8];
            #pragma unroll
            for (int k = 0; k < 8; k++) xv[k] = xs[c][po + 32*k];
            #pragma unroll
            for (int u = 0; u < 8; u++) wv[u] = ws[oi + 8*u][c];
            #pragma unroll
            for (int u = 0; u < 8; u++)
                #pragma unroll
                for (int k = 0; k < 8; k++) acc[u][k] += wv[u] * xv[k];
        }
    }

    const float g = gamma[0];
    #pragma unroll
    for (int u = 0; u < 8; u++) {
        int o = ot + oi + 8*u;
        float bb = bv[o];
        size_t base = ((size_t)b * CC + o) * HW + p0;
        #pragma unroll
        for (int k = 0; k < 8; k++) {
            size_t idx = base + po + 32*k;
            outp[idx] = g * (acc[u][k] + bb) + x1[idx];
        }
    }
}

// ---------------------------------------------------------------------------
extern "C" void kernel_launch(void* const* d_in, const int* in_sizes, int n_in,
                              void* d_out, int out_size)
{
    const float* x0    = (const float*)d_in[0];
    const float* x1    = (const float*)d_in[1];
    const float* Wq    = (const float*)d_in[2];
    const float* bq    = (const float*)d_in[3];
    const float* Wk    = (const float*)d_in[4];
    const float* bk    = (const float*)d_in[5];
    const float* Wv    = (const float*)d_in[6];
    const float* bv    = (const float*)d_in[7];
    const float* gamma = (const float*)d_in[8];
    float* out = (float*)d_out;

    // Output layout: out [B,C,W,H] flattened, then attention [B,B]
    const long long out_elems = (long long)BB * CC * HW;
    float* att_out = ((long long)out_size >= out_elems + BB*BB)
                     ? out + out_elems : nullptr;

    k_zero_energy<<<1, 1024>>>();
    k_proj_qk<<<dim3(HW/256, BB, 2), 256>>>(x0, x1, Wq, bq, Wk, bk);
    k_energy<<<DD/512, 256>>>();
    k_softmax<<<1, 32>>>(att_out);
    k_mix<<<CHW/256, 256>>>(x0);
    k_out<<<dim3(HW/256, BB, CC/64), 256>>>(x1, Wv, bv, gamma, out);
}

// round 7
// speedup vs baseline: 1.2579x; 1.2579x over previous
#include <cuda_runtime.h>
#include <math.h>
#include <stdint.h>

// Problem constants
#define BB   32
#define CC   256
#define CQ   64
#define HW   4096                 // 64*64
#define CHW  (CC*HW)              // 1048576
#define DD   (CQ*HW)              // 262144

// Scratch (device globals — no allocation allowed)
__device__ float g_Q[(size_t)BB*CQ*HW];
__device__ float g_K[(size_t)BB*CQ*HW];
__device__ float g_energy[BB*BB];
__device__ float g_att[BB*BB];
__device__ float g_y[(size_t)BB*CHW];

// Pre-transposed / tf32-split weights: [c][o] layout
__device__ float g_WqT_h[CC*CQ], g_WqT_l[CC*CQ];
__device__ float g_WkT_h[CC*CQ], g_WkT_l[CC*CQ];
__device__ float g_WvT  [CC*CC];

// ---------------------------------------------------------------------------
__device__ __forceinline__ float tf32r(float x) {
    uint32_t u;
    asm("cvt.rna.tf32.f32 %0, %1;" : "=r"(u) : "f"(x));
    return __uint_as_float(u);
}

__device__ __forceinline__ void mma_tf32(
    float& c0, float& c1, float& c2, float& c3,
    uint32_t a0, uint32_t a1, uint32_t a2, uint32_t a3,
    uint32_t b0, uint32_t b1)
{
    asm volatile(
        "mma.sync.aligned.m16n8k8.row.col.f32.tf32.tf32.f32 "
        "{%0,%1,%2,%3}, {%4,%5,%6,%7}, {%8,%9}, {%0,%1,%2,%3};"
        : "+f"(c0), "+f"(c1), "+f"(c2), "+f"(c3)
        : "r"(a0), "r"(a1), "r"(a2), "r"(a3), "r"(b0), "r"(b1));
}

// ---------------------------------------------------------------------------
// Weight prep: transpose to [c][o]; hi/lo tf32 split for Wq/Wk; tf32 round Wv.
__global__ __launch_bounds__(256) void k_prep(
    const float* __restrict__ Wq, const float* __restrict__ Wk,
    const float* __restrict__ Wv)
{
    int t = blockIdx.x * 256 + threadIdx.x;
    int stride = gridDim.x * 256;
    for (int i = t; i < CQ*CC; i += stride) {
        int o = i >> 8, c = i & 255;
        float q = Wq[i];
        float qh = tf32r(q);
        g_WqT_h[c*CQ + o] = qh;
        g_WqT_l[c*CQ + o] = tf32r(q - qh);
        float k = Wk[i];
        float kh = tf32r(k);
        g_WkT_h[c*CQ + o] = kh;
        g_WkT_l[c*CQ + o] = tf32r(k - kh);
    }
    for (int i = t; i < CC*CC; i += stride) {
        int o = i >> 8, c = i & 255;
        g_WvT[c*CC + o] = tf32r(Wv[i]);
    }
}

// ---------------------------------------------------------------------------
__global__ void k_zero_energy() {
    int t = threadIdx.x;
    if (t < BB*BB) g_energy[t] = 0.0f;
}

// ---------------------------------------------------------------------------
// Q = Wq x0 + bq ; K = Wk x1 + bk  via 3xTF32 mma. Tile: 64 o x 128 p.
// 8 warps, each m16(p) x n64(o), k loop over 256 in chunks of 16 (2 ksteps).
__global__ __launch_bounds__(256) void k_proj_tf32(
    const float* __restrict__ x0, const float* __restrict__ x1,
    const float* __restrict__ bq, const float* __restrict__ bk)
{
    const int which = blockIdx.z;
    const float* __restrict__ x    = which ? x1 : x0;
    const float* __restrict__ bias = which ? bk : bq;
    const float* __restrict__ WT_h = which ? g_WkT_h : g_WqT_h;
    const float* __restrict__ WT_l = which ? g_WkT_l : g_WqT_l;
    float* __restrict__ outp       = which ? g_K : g_Q;

    const int b  = blockIdx.y;
    const int p0 = blockIdx.x * 128;
    const int t    = threadIdx.x;
    const int lane = t & 31;
    const int warp = t >> 5;
    const int gid  = lane >> 2;   // groupID 0..7
    const int tig  = lane & 3;    // threadInGroup 0..3
    const int pbase = warp * 16;  // warp m-tile

    // smem union: mainloop buffers (6656 floats) / stage (64x133 = 8512 floats)
    __shared__ float smem[8512];
    float* xs_h = smem;                 // [16][136]
    float* xs_l = smem + 2176;          // [16][136]
    float* ws_h = smem + 4352;          // [16][72]
    float* ws_l = smem + 5504;          // [16][72]
    float* stage = smem;                // [64][133]

    float C[8][4];
    #pragma unroll
    for (int nf = 0; nf < 8; nf++)
        #pragma unroll
        for (int i = 0; i < 4; i++) C[nf][i] = 0.0f;

    const float* xb = x + (size_t)b * CHW + p0;

    for (int cc = 0; cc < CC; cc += 16) {
        __syncthreads();
        // xs fill: 16c x 128p = 512 float4 -> 2 per thread (+ hi/lo split)
        #pragma unroll
        for (int r = 0; r < 2; r++) {
            int idx = r * 256 + t;
            int c = idx >> 5, q4 = idx & 31;
            float4 v = *reinterpret_cast<const float4*>(xb + (size_t)(cc + c) * HW + q4 * 4);
            float4 h, l;
            h.x = tf32r(v.x); l.x = tf32r(v.x - h.x);
            h.y = tf32r(v.y); l.y = tf32r(v.y - h.y);
            h.z = tf32r(v.z); l.z = tf32r(v.z - h.z);
            h.w = tf32r(v.w); l.w = tf32r(v.w - h.w);
            *reinterpret_cast<float4*>(&xs_h[c*136 + q4*4]) = h;
            *reinterpret_cast<float4*>(&xs_l[c*136 + q4*4]) = l;
        }
        // ws fill: 16c x 64o = 256 float4 -> 1 per thread (hi and lo)
        {
            int c = t >> 4, q4 = t & 15;
            *reinterpret_cast<float4*>(&ws_h[c*72 + q4*4]) =
                *reinterpret_cast<const float4*>(&WT_h[(cc + c)*CQ + q4*4]);
            *reinterpret_cast<float4*>(&ws_l[c*72 + q4*4]) =
                *reinterpret_cast<const float4*>(&WT_l[(cc + c)*CQ + q4*4]);
        }
        __syncthreads();

        #pragma unroll
        for (int kk = 0; kk < 2; kk++) {
            const int kb = kk * 8;
            const int ar0 = (kb + tig) * 136;
            const int ar2 = (kb + tig + 4) * 136;
            const int pc  = pbase + gid;
            uint32_t a0h = __float_as_uint(xs_h[ar0 + pc]);
            uint32_t a1h = __float_as_uint(xs_h[ar0 + pc + 8]);
            uint32_t a2h = __float_as_uint(xs_h[ar2 + pc]);
            uint32_t a3h = __float_as_uint(xs_h[ar2 + pc + 8]);
            uint32_t a0l = __float_as_uint(xs_l[ar0 + pc]);
            uint32_t a1l = __float_as_uint(xs_l[ar0 + pc + 8]);
            uint32_t a2l = __float_as_uint(xs_l[ar2 + pc]);
            uint32_t a3l = __float_as_uint(xs_l[ar2 + pc + 8]);
            const int br0 = (kb + tig) * 72;
            const int br1 = (kb + tig + 4) * 72;
            #pragma unroll
            for (int nf = 0; nf < 8; nf++) {
                const int bo = nf * 8 + gid;
                uint32_t b0h = __float_as_uint(ws_h[br0 + bo]);
                uint32_t b1h = __float_as_uint(ws_h[br1 + bo]);
                uint32_t b0l = __float_as_uint(ws_l[br0 + bo]);
                uint32_t b1l = __float_as_uint(ws_l[br1 + bo]);
                mma_tf32(C[nf][0], C[nf][1], C[nf][2], C[nf][3],
                         a0h, a1h, a2h, a3h, b0h, b1h);
                mma_tf32(C[nf][0], C[nf][1], C[nf][2], C[nf][3],
                         a0h, a1h, a2h, a3h, b0l, b1l);
                mma_tf32(C[nf][0], C[nf][1], C[nf][2], C[nf][3],
                         a0l, a1l, a2l, a3l, b0h, b1h);
            }
        }
    }

    // Stage through smem for coalesced output
    __syncthreads();
    #pragma unroll
    for (int nf = 0; nf < 8; nf++) {
        int o = nf * 8 + tig * 2;
        int p = pbase + gid;
        stage[o*133 + p]         = C[nf][0];
        stage[(o+1)*133 + p]     = C[nf][1];
        stage[o*133 + p + 8]     = C[nf][2];
        stage[(o+1)*133 + p + 8] = C[nf][3];
    }
    __syncthreads();
    #pragma unroll
    for (int r = 0; r < 32; r++) {
        int idx = r * 256 + t;
        int o = idx >> 7, p = idx & 127;
        outp[((size_t)b * CQ + o) * HW + p0 + p] = stage[o*133 + p] + bias[o];
    }
}

// ---------------------------------------------------------------------------
// energy[i][j] += sum_d K[i,d] * Q[j,d]
__global__ __launch_bounds__(256) void k_energy()
{
    __shared__ float Ks[32][65];
    __shared__ float Qs[32][65];
    const int t  = threadIdx.x;
    const int jj = t & 15;
    const int ii = t >> 4;

    float acc[2][2] = {{0.f,0.f},{0.f,0.f}};
    const int d0 = blockIdx.x * 512;

    for (int ch = 0; ch < 8; ch++) {
        const int db = d0 + ch * 64;
        __syncthreads();
        #pragma unroll
        for (int r = 0; r < 8; r++) {
            int idx = r * 256 + t;
            int row = idx >> 6, dd = idx & 63;
            Ks[row][dd] = g_K[(size_t)row * DD + db + dd];
            Qs[row][dd] = g_Q[(size_t)row * DD + db + dd];
        }
        __syncthreads();
        #pragma unroll
        for (int dd = 0; dd < 64; dd++) {
            float k0 = Ks[ii][dd],  k1 = Ks[ii + 16][dd];
            float q0 = Qs[jj][dd],  q1 = Qs[jj + 16][dd];
            acc[0][0] += k0 * q0;  acc[0][1] += k0 * q1;
            acc[1][0] += k1 * q0;  acc[1][1] += k1 * q1;
        }
    }
    #pragma unroll
    for (int u = 0; u < 2; u++)
        #pragma unroll
        for (int v = 0; v < 2; v++)
            atomicAdd(&g_energy[(ii + 16*u) * BB + (jj + 16*v)], acc[u][v]);
}

// ---------------------------------------------------------------------------
__global__ void k_softmax(float* __restrict__ att_out)
{
    int i = threadIdx.x;
    if (i >= BB) return;
    float e[BB];
    float m = -INFINITY;
    #pragma unroll
    for (int j = 0; j < BB; j++) { e[j] = g_energy[i*BB + j]; m = fmaxf(m, e[j]); }
    float s = 0.f;
    #pragma unroll
    for (int j = 0; j < BB; j++) { e[j] = expf(e[j] - m); s += e[j]; }
    float inv = 1.0f / s;
    #pragma unroll
    for (int j = 0; j < BB; j++) {
        float a = e[j] * inv;
        g_att[i*BB + j] = a;
        if (att_out) att_out[i*BB + j] = a;
    }
}

// ---------------------------------------------------------------------------
// y[i,cp] = sum_j att[i,j] * x0[j,cp]
__global__ __launch_bounds__(256) void k_mix(const float* __restrict__ x0)
{
    __shared__ float att_s[BB*BB];
    const int t = threadIdx.x;
    #pragma unroll
    for (int r = 0; r < 4; r++) att_s[r*256 + t] = g_att[r*256 + t];
    __syncthreads();

    const size_t cp = (size_t)blockIdx.x * 256 + t;
    float acc[BB];
    #pragma unroll
    for (int i = 0; i < BB; i++) acc[i] = 0.0f;

    #pragma unroll
    for (int j = 0; j < BB; j++) {
        float v = x0[(size_t)j * CHW + cp];
        #pragma unroll
        for (int i = 0; i < BB; i++) acc[i] += att_s[i*BB + j] * v;
    }
    #pragma unroll
    for (int i = 0; i < BB; i++) g_y[(size_t)i * CHW + cp] = acc[i];
}

// ---------------------------------------------------------------------------
// out = gamma*(Wv y + bv) + x1 via single-pass tf32 mma.
// Block tile: 128 o x 128 p. Warps 4(p) x 2(o): warp m32(p) x n64(o).
__global__ __launch_bounds__(256) void k_out_tf32(
    const float* __restrict__ x1, const float* __restrict__ bv,
    const float* __restrict__ gamma, float* __restrict__ outp)
{
    const int b  = blockIdx.y;
    const int ot = blockIdx.z * 128;
    const int p0 = blockIdx.x * 128;
    const int t    = threadIdx.x;
    const int lane = t & 31;
    const int warp = t >> 5;
    const int gid  = lane >> 2;
    const int tig  = lane & 3;
    const int wp = warp & 3;        // p group
    const int wo = warp >> 2;       // o group
    const int pbase = wp * 32;
    const int obase = wo * 64;

    __shared__ float smem[8512];
    float* xs = smem;               // [16][136]
    float* ws = smem + 2176;        // [16][136]
    float* stage = smem;            // [64][133]

    float C[2][8][4];
    #pragma unroll
    for (int mf = 0; mf < 2; mf++)
        #pragma unroll
        for (int nf = 0; nf < 8; nf++)
            #pragma unroll
            for (int i = 0; i < 4; i++) C[mf][nf][i] = 0.0f;

    const float* yb = g_y + (size_t)b * CHW + p0;

    for (int cc = 0; cc < CC; cc += 16) {
        __syncthreads();
        #pragma unroll
        for (int r = 0; r < 2; r++) {
            int idx = r * 256 + t;
            int c = idx >> 5, q4 = idx & 31;
            float4 v = *reinterpret_cast<const float4*>(yb + (size_t)(cc + c) * HW + q4 * 4);
            v.x = tf32r(v.x); v.y = tf32r(v.y); v.z = tf32r(v.z); v.w = tf32r(v.w);
            *reinterpret_cast<float4*>(&xs[c*136 + q4*4]) = v;
        }
        #pragma unroll
        for (int r = 0; r < 2; r++) {
            int idx = r * 256 + t;
            int c = idx >> 5, q4 = idx & 31;
            *reinterpret_cast<float4*>(&ws[c*136 + q4*4]) =
                *reinterpret_cast<const float4*>(&g_WvT[(cc + c)*CC + ot + q4*4]);
        }
        __syncthreads();

        #pragma unroll
        for (int kk = 0; kk < 2; kk++) {
            const int kb = kk * 8;
            const int ar0 = (kb + tig) * 136;
            const int ar2 = (kb + tig + 4) * 136;
            uint32_t A[2][4];
            #pragma unroll
            for (int mf = 0; mf < 2; mf++) {
                const int pc = pbase + mf * 16 + gid;
                A[mf][0] = __float_as_uint(xs[ar0 + pc]);
                A[mf][1] = __float_as_uint(xs[ar0 + pc + 8]);
                A[mf][2] = __float_as_uint(xs[ar2 + pc]);
                A[mf][3] = __float_as_uint(xs[ar2 + pc + 8]);
            }
            #pragma unroll
            for (int nf = 0; nf < 8; nf++) {
                const int bo = obase + nf * 8 + gid;
                uint32_t b0 = __float_as_uint(ws[ar0 + bo]);
                uint32_t b1 = __float_as_uint(ws[ar2 + bo]);
                #pragma unroll
                for (int mf = 0; mf < 2; mf++)
                    mma_tf32(C[mf][nf][0], C[mf][nf][1], C[mf][nf][2], C[mf][nf][3],
                             A[mf][0], A[mf][1], A[mf][2], A[mf][3], b0, b1);
            }
        }
    }

    const float g = gamma[0];
    // Two-half staged epilogue (o 0..63, then 64..127 within this o-tile)
    #pragma unroll
    for (int h = 0; h < 2; h++) {
        __syncthreads();
        if (wo == h) {
            #pragma unroll
            for (int mf = 0; mf < 2; mf++)
                #pragma unroll
                for (int nf = 0; nf < 8; nf++) {
                    int ol = nf * 8 + tig * 2;
                    int p = pbase + mf * 16 + gid;
                    stage[ol*133 + p]         = C[mf][nf][0];
                    stage[(ol+1)*133 + p]     = C[mf][nf][1];
                    stage[ol*133 + p + 8]     = C[mf][nf][2];
                    stage[(ol+1)*133 + p + 8] = C[mf][nf][3];
                }
        }
        __syncthreads();
        #pragma unroll
        for (int r = 0; r < 32; r++) {
            int idx = r * 256 + t;
            int ol = idx >> 7, p = idx & 127;
            int o = ot + h * 64 + ol;
            size_t gi = ((size_t)b * CC + o) * HW + p0 + p;
            outp[gi] = g * (stage[ol*133 + p] + bv[o]) + x1[gi];
        }
    }
}

// ---------------------------------------------------------------------------
extern "C" void kernel_launch(void* const* d_in, const int* in_sizes, int n_in,
                              void* d_out, int out_size)
{
    const float* x0    = (const float*)d_in[0];
    const float* x1    = (const float*)d_in[1];
    const float* Wq    = (const float*)d_in[2];
    const float* bq    = (const float*)d_in[3];
    const float* Wk    = (const float*)d_in[4];
    const float* bk    = (const float*)d_in[5];
    const float* Wv    = (const float*)d_in[6];
    const float* bv    = (const float*)d_in[7];
    const float* gamma = (const float*)d_in[8];
    float* out = (float*)d_out;

    const long long out_elems = (long long)BB * CC * HW;
    float* att_out = ((long long)out_size >= out_elems + BB*BB)
                     ? out + out_elems : nullptr;

    k_prep<<<32, 256>>>(Wq, Wk, Wv);
    k_zero_energy<<<1, 1024>>>();
    k_proj_tf32<<<dim3(HW/128, BB, 2), 256>>>(x0, x1, bq, bk);
    k_energy<<<DD/512, 256>>>();
    k_softmax<<<1, 32>>>(att_out);
    k_mix<<<CHW/256, 256>>>(x0);
    k_out_tf32<<<dim3(HW/128, BB, CC/64 /2), 256>>>(x1, bv, gamma, out);
}

// round 8
// speedup vs baseline: 1.5166x; 1.2056x over previous
#include <cuda_runtime.h>
#include <cuda_bf16.h>
#include <math.h>
#include <stdint.h>

// Problem constants
#define BB   32
#define CC   256
#define CQ   64
#define HW   4096                 // 64*64
#define CHW  (CC*HW)              // 1048576
#define DD   (CQ*HW)              // 262144

// Scratch (device globals — no allocation allowed)
__device__ float g_Q[(size_t)BB*CQ*HW];
__device__ float g_K[(size_t)BB*CQ*HW];
__device__ float g_energy[BB*BB];
__device__ float g_att[BB*BB];
__device__ uint4 g_y_bf[(size_t)BB*CHW/8];    // bf16 [i][c][p]
__device__ uint4 g_Wv_bf[CC*CC/8];            // bf16 [o][c]

// tf32-split weights for Q/K: [c][o]
__device__ float g_WqT_h[CC*CQ], g_WqT_l[CC*CQ];
__device__ float g_WkT_h[CC*CQ], g_WkT_l[CC*CQ];

// ---------------------------------------------------------------------------
__device__ __forceinline__ float tf32r(float x) {
    uint32_t u;
    asm("cvt.rna.tf32.f32 %0, %1;" : "=r"(u) : "f"(x));
    return __uint_as_float(u);
}

__device__ __forceinline__ void mma_tf32(
    float& c0, float& c1, float& c2, float& c3,
    uint32_t a0, uint32_t a1, uint32_t a2, uint32_t a3,
    uint32_t b0, uint32_t b1)
{
    asm volatile(
        "mma.sync.aligned.m16n8k8.row.col.f32.tf32.tf32.f32 "
        "{%0,%1,%2,%3}, {%4,%5,%6,%7}, {%8,%9}, {%0,%1,%2,%3};"
        : "+f"(c0), "+f"(c1), "+f"(c2), "+f"(c3)
        : "r"(a0), "r"(a1), "r"(a2), "r"(a3), "r"(b0), "r"(b1));
}

__device__ __forceinline__ void mma_bf16(
    float* c, const uint32_t* a, uint32_t b0, uint32_t b1)
{
    asm volatile(
        "mma.sync.aligned.m16n8k16.row.col.f32.bf16.bf16.f32 "
        "{%0,%1,%2,%3}, {%4,%5,%6,%7}, {%8,%9}, {%0,%1,%2,%3};"
        : "+f"(c[0]), "+f"(c[1]), "+f"(c[2]), "+f"(c[3])
        : "r"(a[0]), "r"(a[1]), "r"(a[2]), "r"(a[3]), "r"(b0), "r"(b1));
}

__device__ __forceinline__ void ldsm_x4(
    uint32_t& r0, uint32_t& r1, uint32_t& r2, uint32_t& r3, uint32_t addr)
{
    asm volatile("ldmatrix.sync.aligned.m8n8.x4.shared.b16 {%0,%1,%2,%3}, [%4];"
        : "=r"(r0), "=r"(r1), "=r"(r2), "=r"(r3) : "r"(addr));
}

__device__ __forceinline__ void ldsm_x4_t(
    uint32_t& r0, uint32_t& r1, uint32_t& r2, uint32_t& r3, uint32_t addr)
{
    asm volatile("ldmatrix.sync.aligned.m8n8.x4.trans.shared.b16 {%0,%1,%2,%3}, [%4];"
        : "=r"(r0), "=r"(r1), "=r"(r2), "=r"(r3) : "r"(addr));
}

// ---------------------------------------------------------------------------
// Weight prep: Wq/Wk -> transposed tf32 hi/lo split; Wv -> bf16 [o][c].
__global__ __launch_bounds__(256) void k_prep(
    const float* __restrict__ Wq, const float* __restrict__ Wk,
    const float* __restrict__ Wv)
{
    int t = blockIdx.x * 256 + threadIdx.x;
    int stride = gridDim.x * 256;
    for (int i = t; i < CQ*CC; i += stride) {
        int o = i >> 8, c = i & 255;
        float q = Wq[i];
        float qh = tf32r(q);
        g_WqT_h[c*CQ + o] = qh;
        g_WqT_l[c*CQ + o] = tf32r(q - qh);
        float k = Wk[i];
        float kh = tf32r(k);
        g_WkT_h[c*CQ + o] = kh;
        g_WkT_l[c*CQ + o] = tf32r(k - kh);
    }
    __nv_bfloat16* wv = (__nv_bfloat16*)g_Wv_bf;
    for (int i = t; i < CC*CC; i += stride)
        wv[i] = __float2bfloat16(Wv[i]);
}

// ---------------------------------------------------------------------------
__global__ void k_zero_energy() {
    int t = threadIdx.x;
    if (t < BB*BB) g_energy[t] = 0.0f;
}

// ---------------------------------------------------------------------------
// Q = Wq x0 + bq ; K = Wk x1 + bk via 3xTF32 mma.
// Block: 64 o x 256 p, 8 warps, warp tile m32(p) x n64(o).
__global__ __launch_bounds__(256) void k_proj_tf32(
    const float* __restrict__ x0, const float* __restrict__ x1,
    const float* __restrict__ bq, const float* __restrict__ bk)
{
    const int which = blockIdx.z;
    const float* __restrict__ x    = which ? x1 : x0;
    const float* __restrict__ bias = which ? bk : bq;
    const float* __restrict__ WT_h = which ? g_WkT_h : g_WqT_h;
    const float* __restrict__ WT_l = which ? g_WkT_l : g_WqT_l;
    float* __restrict__ outp       = which ? g_K : g_Q;

    const int b  = blockIdx.y;
    const int p0 = blockIdx.x * 256;
    const int t    = threadIdx.x;
    const int lane = t & 31;
    const int warp = t >> 5;
    const int gid  = lane >> 2;
    const int tig  = lane & 3;
    const int pbase = warp * 32;

    // smem union: xs_h[16][264], xs_l[16][264], ws_h[16][72], ws_l[16][72]
    //             / stage[64][132]
    __shared__ float sm[10752];
    float* xs_h = sm;                  // 4224
    float* xs_l = sm + 4224;           // 4224
    float* ws_h = sm + 8448;           // 1152
    float* ws_l = sm + 9600;           // 1152
    float* stage = sm;                 // 8448

    float C[2][8][4];
    #pragma unroll
    for (int mf = 0; mf < 2; mf++)
        #pragma unroll
        for (int nf = 0; nf < 8; nf++)
            #pragma unroll
            for (int i = 0; i < 4; i++) C[mf][nf][i] = 0.0f;

    const float* xb = x + (size_t)b * CHW + p0;

    for (int cc = 0; cc < CC; cc += 16) {
        __syncthreads();
        // xs: 16c x 256p = 1024 float4 -> 4/thread, tf32 hi/lo split
        #pragma unroll
        for (int r = 0; r < 4; r++) {
            int idx = r * 256 + t;
            int c = idx >> 6, q4 = idx & 63;
            float4 v = *reinterpret_cast<const float4*>(xb + (size_t)(cc + c) * HW + q4 * 4);
            float4 h, l;
            h.x = tf32r(v.x); l.x = tf32r(v.x - h.x);
            h.y = tf32r(v.y); l.y = tf32r(v.y - h.y);
            h.z = tf32r(v.z); l.z = tf32r(v.z - h.z);
            h.w = tf32r(v.w); l.w = tf32r(v.w - h.w);
            *reinterpret_cast<float4*>(&xs_h[c*264 + q4*4]) = h;
            *reinterpret_cast<float4*>(&xs_l[c*264 + q4*4]) = l;
        }
        // ws: 16c x 64o = 256 float4 -> 1/thread (hi and lo)
        {
            int c = t >> 4, q4 = t & 15;
            *reinterpret_cast<float4*>(&ws_h[c*72 + q4*4]) =
                *reinterpret_cast<const float4*>(&WT_h[(cc + c)*CQ + q4*4]);
            *reinterpret_cast<float4*>(&ws_l[c*72 + q4*4]) =
                *reinterpret_cast<const float4*>(&WT_l[(cc + c)*CQ + q4*4]);
        }
        __syncthreads();

        #pragma unroll
        for (int kk = 0; kk < 2; kk++) {
            const int kb = kk * 8;
            const int ar0 = (kb + tig) * 264;
            const int ar2 = (kb + tig + 4) * 264;
            uint32_t Ah[2][4], Al[2][4];
            #pragma unroll
            for (int mf = 0; mf < 2; mf++) {
                const int pc = pbase + mf * 16 + gid;
                Ah[mf][0] = __float_as_uint(xs_h[ar0 + pc]);
                Ah[mf][1] = __float_as_uint(xs_h[ar0 + pc + 8]);
                Ah[mf][2] = __float_as_uint(xs_h[ar2 + pc]);
                Ah[mf][3] = __float_as_uint(xs_h[ar2 + pc + 8]);
                Al[mf][0] = __float_as_uint(xs_l[ar0 + pc]);
                Al[mf][1] = __float_as_uint(xs_l[ar0 + pc + 8]);
                Al[mf][2] = __float_as_uint(xs_l[ar2 + pc]);
                Al[mf][3] = __float_as_uint(xs_l[ar2 + pc + 8]);
            }
            const int br0 = (kb + tig) * 72;
            const int br1 = (kb + tig + 4) * 72;
            #pragma unroll
            for (int nf = 0; nf < 8; nf++) {
                const int bo = nf * 8 + gid;
                uint32_t b0h = __float_as_uint(ws_h[br0 + bo]);
                uint32_t b1h = __float_as_uint(ws_h[br1 + bo]);
                uint32_t b0l = __float_as_uint(ws_l[br0 + bo]);
                uint32_t b1l = __float_as_uint(ws_l[br1 + bo]);
                #pragma unroll
                for (int mf = 0; mf < 2; mf++) {
                    mma_tf32(C[mf][nf][0], C[mf][nf][1], C[mf][nf][2], C[mf][nf][3],
                             Ah[mf][0], Ah[mf][1], Ah[mf][2], Ah[mf][3], b0h, b1h);
                    mma_tf32(C[mf][nf][0], C[mf][nf][1], C[mf][nf][2], C[mf][nf][3],
                             Ah[mf][0], Ah[mf][1], Ah[mf][2], Ah[mf][3], b0l, b1l);
                    mma_tf32(C[mf][nf][0], C[mf][nf][1], C[mf][nf][2], C[mf][nf][3],
                             Al[mf][0], Al[mf][1], Al[mf][2], Al[mf][3], b0h, b1h);
                }
            }
        }
    }

    // Epilogue in two p-half phases through stage[64][132]
    #pragma unroll
    for (int h = 0; h < 2; h++) {
        __syncthreads();
        if ((warp >> 2) == h) {
            const int lp0 = pbase - h * 128;
            #pragma unroll
            for (int mf = 0; mf < 2; mf++)
                #pragma unroll
                for (int nf = 0; nf < 8; nf++) {
                    int o = nf * 8 + tig * 2;
                    int lp = lp0 + mf * 16 + gid;
                    stage[o*132 + lp]         = C[mf][nf][0];
                    stage[(o+1)*132 + lp]     = C[mf][nf][1];
                    stage[o*132 + lp + 8]     = C[mf][nf][2];
                    stage[(o+1)*132 + lp + 8] = C[mf][nf][3];
                }
        }
        __syncthreads();
        #pragma unroll
        for (int r = 0; r < 32; r++) {
            int idx = r * 256 + t;
            int o = idx >> 7, p = idx & 127;
            outp[((size_t)b * CQ + o) * HW + p0 + h*128 + p] = stage[o*132 + p] + bias[o];
        }
    }
}

// ---------------------------------------------------------------------------
// energy[i][j] += sum_d K[i,d] * Q[j,d].  64 thr/block, 4x4 register tile,
// direct float4 LDG (broadcast-coalesced), no smem.
__global__ __launch_bounds__(64) void k_energy()
{
    const int t  = threadIdx.x;
    const int tj = t & 7;
    const int ti = t >> 3;
    const int d0 = blockIdx.x * 512;

    float acc[4][4];
    #pragma unroll
    for (int r = 0; r < 4; r++)
        #pragma unroll
        for (int s = 0; s < 4; s++) acc[r][s] = 0.0f;

    for (int d = d0; d < d0 + 512; d += 4) {
        float4 kv[4], qv[4];
        #pragma unroll
        for (int r = 0; r < 4; r++)
            kv[r] = *reinterpret_cast<const float4*>(&g_K[(size_t)(ti + 8*r) * DD + d]);
        #pragma unroll
        for (int s = 0; s < 4; s++)
            qv[s] = *reinterpret_cast<const float4*>(&g_Q[(size_t)(tj + 8*s) * DD + d]);
        #pragma unroll
        for (int r = 0; r < 4; r++)
            #pragma unroll
            for (int s = 0; s < 4; s++)
                acc[r][s] += kv[r].x*qv[s].x + kv[r].y*qv[s].y
                           + kv[r].z*qv[s].z + kv[r].w*qv[s].w;
    }
    #pragma unroll
    for (int r = 0; r < 4; r++)
        #pragma unroll
        for (int s = 0; s < 4; s++)
            atomicAdd(&g_energy[(ti + 8*r) * BB + (tj + 8*s)], acc[r][s]);
}

// ---------------------------------------------------------------------------
__global__ void k_softmax(float* __restrict__ att_out)
{
    int i = threadIdx.x;
    if (i >= BB) return;
    float e[BB];
    float m = -INFINITY;
    #pragma unroll
    for (int j = 0; j < BB; j++) { e[j] = g_energy[i*BB + j]; m = fmaxf(m, e[j]); }
    float s = 0.f;
    #pragma unroll
    for (int j = 0; j < BB; j++) { e[j] = expf(e[j] - m); s += e[j]; }
    float inv = 1.0f / s;
    #pragma unroll
    for (int j = 0; j < BB; j++) {
        float a = e[j] * inv;
        g_att[i*BB + j] = a;
        if (att_out) att_out[i*BB + j] = a;
    }
}

// ---------------------------------------------------------------------------
// y[i,cp] = sum_j att[i,j] * x0[j,cp]; write bf16.
__global__ __launch_bounds__(256) void k_mix(const float* __restrict__ x0)
{
    __shared__ float att_s[BB*BB];
    const int t = threadIdx.x;
    #pragma unroll
    for (int r = 0; r < 4; r++) att_s[r*256 + t] = g_att[r*256 + t];
    __syncthreads();

    const size_t cp = (size_t)blockIdx.x * 256 + t;
    float acc[BB];
    #pragma unroll
    for (int i = 0; i < BB; i++) acc[i] = 0.0f;

    #pragma unroll
    for (int j = 0; j < BB; j++) {
        float v = x0[(size_t)j * CHW + cp];
        #pragma unroll
        for (int i = 0; i < BB; i++) acc[i] += att_s[i*BB + j] * v;
    }
    __nv_bfloat16* y = (__nv_bfloat16*)g_y_bf;
    #pragma unroll
    for (int i = 0; i < BB; i++)
        y[(size_t)i * CHW + cp] = __float2bfloat16(acc[i]);
}

// ---------------------------------------------------------------------------
// out = gamma*(Wv y + bv) + x1 via bf16 m16n8k16 mma + ldmatrix.
// Block: 64 o x 128 p; 8 warps = 2(o) x 4(p); warp tile m32(o) x n32(p).
__global__ __launch_bounds__(256) void k_out_bf16(
    const float* __restrict__ x1, const float* __restrict__ bv,
    const float* __restrict__ gamma, float* __restrict__ outp)
{
    const int b  = blockIdx.y;
    const int ot = blockIdx.z * 64;
    const int p0 = blockIdx.x * 128;
    const int t    = threadIdx.x;
    const int lane = t & 31;
    const int warp = t >> 5;
    const int wo = warp >> 2;       // 0..1
    const int wp = warp & 3;        // 0..3
    const int obase = wo * 32;
    const int pbw   = wp * 32;
    const int gid = lane >> 2;
    const int tig = lane & 3;

    __shared__ __align__(16) uint16_t ws[64*40];   // [o][c] stride 40 bf16 (80B)
    __shared__ __align__(16) uint16_t ys[32*136];  // [c][p] stride 136 bf16 (272B)
    const uint32_t ws_b = (uint32_t)__cvta_generic_to_shared(ws);
    const uint32_t ys_b = (uint32_t)__cvta_generic_to_shared(ys);

    float C[2][4][4];
    #pragma unroll
    for (int mf = 0; mf < 2; mf++)
        #pragma unroll
        for (int nf = 0; nf < 4; nf++)
            #pragma unroll
            for (int i = 0; i < 4; i++) C[mf][nf][i] = 0.0f;

    const __nv_bfloat16* ybase = (const __nv_bfloat16*)g_y_bf + (size_t)b * CHW + p0;
    const __nv_bfloat16* wvb   = (const __nv_bfloat16*)g_Wv_bf;

    for (int cc = 0; cc < CC; cc += 32) {
        __syncthreads();
        // ws: 64 o x 32 c bf16 (one uint4 per thread)
        {
            int row = t >> 2, ch = t & 3;
            *reinterpret_cast<uint4*>(&ws[row*40 + ch*8]) =
                *reinterpret_cast<const uint4*>(wvb + (size_t)(ot + row)*CC + cc + ch*8);
        }
        // ys: 32 c x 128 p bf16 (two uint4 per thread)
        #pragma unroll
        for (int r = 0; r < 2; r++) {
            int idx = r * 256 + t;
            int row = idx >> 4, ch = idx & 15;
            *reinterpret_cast<uint4*>(&ys[row*136 + ch*8]) =
                *reinterpret_cast<const uint4*>(ybase + (size_t)(cc + row)*HW + ch*8);
        }
        __syncthreads();

        #pragma unroll
        for (int kk = 0; kk < 2; kk++) {
            const int rsel = lane & 15;
            const int half = lane >> 4;
            uint32_t A[2][4];
            #pragma unroll
            for (int mf = 0; mf < 2; mf++) {
                uint32_t addr = ws_b + (uint32_t)((obase + mf*16 + rsel)*80 + kk*32 + half*16);
                ldsm_x4(A[mf][0], A[mf][1], A[mf][2], A[mf][3], addr);
            }
            uint32_t Bf[2][4];
            #pragma unroll
            for (int n2 = 0; n2 < 2; n2++) {
                uint32_t addr = ys_b + (uint32_t)((kk*16 + rsel)*272 + (pbw + n2*16 + half*8)*2);
                ldsm_x4_t(Bf[n2][0], Bf[n2][1], Bf[n2][2], Bf[n2][3], addr);
            }
            #pragma unroll
            for (int mf = 0; mf < 2; mf++)
                #pragma unroll
                for (int nf = 0; nf < 4; nf++)
                    mma_bf16(C[mf][nf], A[mf],
                             Bf[nf>>1][(nf&1)*2], Bf[nf>>1][(nf&1)*2 + 1]);
        }
    }

    const float g = gamma[0];
    #pragma unroll
    for (int mf = 0; mf < 2; mf++) {
        const int o = ot + obase + mf*16 + gid;
        const float bv0 = bv[o], bv1 = bv[o + 8];
        #pragma unroll
        for (int nf = 0; nf < 4; nf++) {
            const int p = p0 + pbw + nf*8 + tig*2;
            size_t gi0 = ((size_t)b * CC + o) * HW + p;
            size_t gi1 = gi0 + (size_t)8 * HW;
            float2 xa = *reinterpret_cast<const float2*>(&x1[gi0]);
            float2 xc = *reinterpret_cast<const float2*>(&x1[gi1]);
            float2 r0, r1;
            r0.x = g * (C[mf][nf][0] + bv0) + xa.x;
            r0.y = g * (C[mf][nf][1] + bv0) + xa.y;
            r1.x = g * (C[mf][nf][2] + bv1) + xc.x;
            r1.y = g * (C[mf][nf][3] + bv1) + xc.y;
            *reinterpret_cast<float2*>(&outp[gi0]) = r0;
            *reinterpret_cast<float2*>(&outp[gi1]) = r1;
        }
    }
}

// ---------------------------------------------------------------------------
extern "C" void kernel_launch(void* const* d_in, const int* in_sizes, int n_in,
                              void* d_out, int out_size)
{
    const float* x0    = (const float*)d_in[0];
    const float* x1    = (const float*)d_in[1];
    const float* Wq    = (const float*)d_in[2];
    const float* bq    = (const float*)d_in[3];
    const float* Wk    = (const float*)d_in[4];
    const float* bk    = (const float*)d_in[5];
    const float* Wv    = (const float*)d_in[6];
    const float* bv    = (const float*)d_in[7];
    const float* gamma = (const float*)d_in[8];
    float* out = (float*)d_out;

    const long long out_elems = (long long)BB * CC * HW;
    float* att_out = ((long long)out_size >= out_elems + BB*BB)
                     ? out + out_elems : nullptr;

    k_prep<<<32, 256>>>(Wq, Wk, Wv);
    k_zero_energy<<<1, 1024>>>();
    k_proj_tf32<<<dim3(HW/256, BB, 2), 256>>>(x0, x1, bq, bk);
    k_energy<<<DD/512, 64>>>();
    k_softmax<<<1, 32>>>(att_out);
    k_mix<<<CHW/256, 256>>>(x0);
    k_out_bf16<<<dim3(HW/128, BB, CC/64), 256>>>(x1, bv, gamma, out);
}